// round 15
// baseline (speedup 1.0000x reference)
#include <cuda_runtime.h>
#include <cuda_fp16.h>
#include <cstdint>

#define B_   2
#define T_   2048
#define DM_  1024
#define H_   16
#define DH_  64
#define BT_  (B_ * T_)   // 4096

// Scratch (allocation-free rule: device globals) — all single fp16
__device__ __half g_x[BT_ * DM_];
__device__ __half g_w[4 * DM_ * DM_];                 // W fp16, [K,N], 4 slabs
__device__ __half g_q[BT_ * DM_];
__device__ __half g_k[BT_ * DM_];
__device__ __half g_v[BT_ * DM_];
__device__ __half g_z[BT_ * DM_];

// ===========================================================================
// Warp-MMA + cp.async helpers
// ===========================================================================
__device__ __forceinline__ uint32_t smem_u32(const void* p) {
    uint32_t a;
    asm("{ .reg .u64 t; cvta.to.shared.u64 t, %1; cvt.u32.u64 %0, t; }"
        : "=r"(a) : "l"(p));
    return a;
}

__device__ __forceinline__ void ldsm4(uint32_t* r, uint32_t addr) {
    asm volatile("ldmatrix.sync.aligned.m8n8.x4.shared.b16 {%0,%1,%2,%3}, [%4];"
                 : "=r"(r[0]), "=r"(r[1]), "=r"(r[2]), "=r"(r[3]) : "r"(addr));
}
__device__ __forceinline__ void ldsm4t(uint32_t* r, uint32_t addr) {
    asm volatile("ldmatrix.sync.aligned.m8n8.x4.trans.shared.b16 {%0,%1,%2,%3}, [%4];"
                 : "=r"(r[0]), "=r"(r[1]), "=r"(r[2]), "=r"(r[3]) : "r"(addr));
}

__device__ __forceinline__ void mma16816h(float* c, const uint32_t* a,
                                          const uint32_t* b) {
    asm volatile(
        "mma.sync.aligned.m16n8k16.row.col.f32.f16.f16.f32 "
        "{%0,%1,%2,%3}, {%4,%5,%6,%7}, {%8,%9}, {%0,%1,%2,%3};"
        : "+f"(c[0]), "+f"(c[1]), "+f"(c[2]), "+f"(c[3])
        : "r"(a[0]), "r"(a[1]), "r"(a[2]), "r"(a[3]), "r"(b[0]), "r"(b[1]));
}

#define CP_ASYNC16(dst, src) \
    asm volatile("cp.async.cg.shared.global [%0], [%1], 16;" :: "r"(dst), "l"(src))
#define CP_COMMIT() asm volatile("cp.async.commit_group;")
#define CP_WAIT1()  asm volatile("cp.async.wait_group 1;")
#define CP_WAIT0()  asm volatile("cp.async.wait_group 0;")

__device__ __forceinline__ float ex2f(float x) {
    float y;
    asm("ex2.approx.f32 %0, %1;" : "=f"(y) : "f"(x));
    return y;
}

__device__ __forceinline__ uint32_t pack_h2(float x, float y) {
    __half2 h = __floats2half2_rn(x, y);
    return *(uint32_t*)&h;
}

// ===========================================================================
// Fused conversion kernel (x + 4 weight slabs), fp32 -> fp16
// ===========================================================================
__global__ void conv_all(const float* __restrict__ x,
                         const float* __restrict__ W0, const float* __restrict__ W1,
                         const float* __restrict__ W2, const float* __restrict__ W3,
                         __half* __restrict__ xo, __half* __restrict__ wo)
{
    int y = blockIdx.y;
    if (y < 4) {
        const float* src = (y == 0) ? W0 : (y == 1) ? W1 : (y == 2) ? W2 : W3;
        size_t i = (size_t)(blockIdx.x * 256 + threadIdx.x) * 4;
        float4 v = *(const float4*)(src + i);
        *(uint2*)(wo + (size_t)y * DM_ * DM_ + i) =
            make_uint2(pack_h2(v.x, v.y), pack_h2(v.z, v.w));
    } else {
        size_t i = ((size_t)(y - 4) * 1024 + blockIdx.x) * 1024 +
                   (size_t)threadIdx.x * 4;
        float4 v = *(const float4*)(x + i);
        *(uint2*)(xo + i) = make_uint2(pack_h2(v.x, v.y), pack_h2(v.z, v.w));
    }
}

// ===========================================================================
// fp16 single-pass GEMM: 128x128 tile, BK=64, cp.async 3-stage ring,
// one __syncthreads per k-iteration (16 iters). 2 CTA/SM.
// MODE 0: QKV (widx = blockIdx.x>>3) — RoPE epilogue. MODE 1: out-proj.
// ===========================================================================
#define GPA     144                   // A smem row pitch (64 fp16 + 16B pad)
#define TSZA    (128 * GPA)           // 18432
#define PITB    272                   // B smem row pitch (128 fp16 + 16B pad)
#define TSZB    (64 * PITB)           // 17408
#define STG     (TSZA + TSZB)         // 35840 per stage
#define G_SMEM  (3 * STG)             // 107520

#define QSCALE  0.1803368801111204f   // 0.125 * log2(e)

template<int MODE>
__global__ __launch_bounds__(256, 2) void gemm128(
    const __half* __restrict__ Ap, const __half* __restrict__ Wp,
    const float* __restrict__ cs, const float* __restrict__ sn,
    float* __restrict__ Cf,
    __half* __restrict__ qq, __half* __restrict__ kq, __half* __restrict__ vq)
{
    extern __shared__ __align__(16) char sm[];
    const int tid  = threadIdx.x;
    const int wid  = tid >> 5;
    const int lane = tid & 31;
    const int wm   = wid & 3;
    const int wn   = wid >> 2;
    const int widx = (MODE == 0) ? (blockIdx.x >> 3) : 3;
    const int n0   = (blockIdx.x & 7) * 128;
    const int m0   = blockIdx.y * 128;
    const uint32_t sb = smem_u32(sm);

    const __half* gA = Ap + (size_t)m0 * DM_;
    const __half* gW = Wp + (size_t)widx * DM_ * DM_ + n0;

    const int ar = tid >> 1, ah = tid & 1;   // A: 2 thr/row, 64B each
    const int br = tid >> 2, bq = tid & 3;   // B: 4 thr/row, 64B each

    #define ISSUE(st_, k0_)                                                    \
        {                                                                      \
            uint32_t dA = sb + (st_) * STG + ar * GPA + ah * 64;               \
            const __half* ga = gA + (size_t)ar * DM_ + (k0_) + ah * 32;        \
            CP_ASYNC16(dA,      ga);                                           \
            CP_ASYNC16(dA + 16, ga + 8);                                       \
            CP_ASYNC16(dA + 32, ga + 16);                                      \
            CP_ASYNC16(dA + 48, ga + 24);                                      \
            uint32_t dB = sb + (st_) * STG + TSZA + br * PITB + bq * 64;       \
            const __half* gb = gW + (size_t)((k0_) + br) * DM_ + bq * 32;      \
            CP_ASYNC16(dB,      gb);                                           \
            CP_ASYNC16(dB + 16, gb + 8);                                       \
            CP_ASYNC16(dB + 32, gb + 16);                                      \
            CP_ASYNC16(dB + 48, gb + 24);                                      \
            CP_COMMIT();                                                       \
        }

    const uint32_t a_off = (uint32_t)((lane & 15) * GPA + (lane >> 4) * 16);
    const uint32_t b_off = (uint32_t)((lane & 7) * PITB +
                                      ((lane >> 3) & 1) * 8 * PITB + (lane >> 4) * 16);

    float acc[2][8][4];
    #pragma unroll
    for (int i = 0; i < 2; i++)
        #pragma unroll
        for (int j = 0; j < 8; j++)
            #pragma unroll
            for (int l = 0; l < 4; l++) acc[i][j][l] = 0.f;

    ISSUE(0, 0);
    ISSUE(1, 64);

    const int NIT = DM_ / 64;   // 16
    for (int c = 0; c < NIT; c++) {
        if (c + 1 < NIT) { CP_WAIT1(); } else { CP_WAIT0(); }
        __syncthreads();
        if (c + 2 < NIT) { ISSUE((c + 2) % 3, (c + 2) * 64); }

        const uint32_t stb = sb + (c % 3) * STG;
        #pragma unroll
        for (int ks = 0; ks < 4; ks++) {
            uint32_t af[2][4];
            #pragma unroll
            for (int mt = 0; mt < 2; mt++)
                ldsm4(af[mt], stb + (uint32_t)((wm * 32 + mt * 16) * GPA + ks * 32) + a_off);
            #pragma unroll
            for (int nt = 0; nt < 4; nt++) {
                uint32_t bb = stb + TSZA + (uint32_t)(ks * 16 * PITB +
                              wn * 128 + nt * 32) + b_off;
                uint32_t th[4];
                ldsm4t(th, bb);
                #pragma unroll
                for (int mt = 0; mt < 2; mt++) {
                    mma16816h(acc[mt][2*nt],   af[mt], th);
                    mma16816h(acc[mt][2*nt+1], af[mt], th + 2);
                }
            }
        }
    }

    // ---- epilogue ----
    if (MODE == 1) {
        #pragma unroll
        for (int mt = 0; mt < 2; mt++) {
            int m = m0 + wm * 32 + mt * 16 + (lane >> 2);
            #pragma unroll
            for (int nt = 0; nt < 8; nt++) {
                int n = n0 + wn * 64 + nt * 8 + (lane & 3) * 2;
                *(float2*)(Cf + (size_t)m * DM_ + n) =
                    make_float2(acc[mt][nt][0], acc[mt][nt][1]);
                *(float2*)(Cf + (size_t)(m + 8) * DM_ + n) =
                    make_float2(acc[mt][nt][2], acc[mt][nt][3]);
            }
        }
    } else {
        __half* d = (widx == 0) ? qq : (widx == 1) ? kq : vq;
        #pragma unroll
        for (int mt = 0; mt < 2; mt++) {
            int m  = m0 + wm * 32 + mt * 16 + (lane >> 2);
            int t0 = m & (T_ - 1);
            int t1 = (m + 8) & (T_ - 1);
            #pragma unroll
            for (int nt = 0; nt < 8; nt++) {
                int n = n0 + wn * 64 + nt * 8 + (lane & 3) * 2;
                float e0 = acc[mt][nt][0], o0 = acc[mt][nt][1];
                float e1 = acc[mt][nt][2], o1 = acc[mt][nt][3];
                if (widx <= 1) {
                    int i = (n & 63) >> 1;
                    float c0 = __ldg(cs + t0 * 32 + i), s0 = __ldg(sn + t0 * 32 + i);
                    float c1 = __ldg(cs + t1 * 32 + i), s1 = __ldg(sn + t1 * 32 + i);
                    float sc = (widx == 0) ? QSCALE : 1.f;
                    float a0 = (e0 * c0 - o0 * s0) * sc, b0 = (e0 * s0 + o0 * c0) * sc;
                    float a1 = (e1 * c1 - o1 * s1) * sc, b1 = (e1 * s1 + o1 * c1) * sc;
                    e0 = a0; o0 = b0; e1 = a1; o1 = b1;
                }
                *(uint32_t*)(d + (size_t)m * DM_ + n)       = pack_h2(e0, o0);
                *(uint32_t*)(d + (size_t)(m + 8) * DM_ + n) = pack_h2(e1, o1);
            }
        }
    }
    #undef ISSUE
}

// ===========================================================================
// Tensor-core flash attention (fp16 single-pass, causal, exp2 SOFF=0).
// R12 configuration (best known): 8 warps x 16 q-rows, per-strip fused
// QK->softmax->PV, 3-stage cp.async ring, one sync per k-tile, 2 CTA/SM.
// Balanced CTA pairs (15-bx, bx): 34 k-tiles each.
// ===========================================================================
#define PIT   144
#define V_O   9216
#define AST   18432                 // stage size (K + V tiles)
#define ATT_SMEM (3 * AST)          // 55296

__global__ __launch_bounds__(256, 2) void attn_mma(
    const __half* __restrict__ qq, const __half* __restrict__ kq,
    const __half* __restrict__ vq, __half* __restrict__ zq)
{
    extern __shared__ __align__(16) char sm[];
    const int tid  = threadIdx.x;
    const int lane = tid & 31;
    const int wq   = tid >> 5;
    const int bx   = blockIdx.x;          // 0..7
    const int bh_  = blockIdx.y;
    const int b    = bh_ >> 4;
    const int h    = bh_ & 15;
    const int bT   = b * T_;
    const uint32_t sb = smem_u32(sm);
    const size_t hcol = (size_t)h * DH_;

    const uint32_t k_off = ((lane >> 4) * 8 + (lane & 7)) * PIT + ((lane >> 3) & 1) * 16;
    const uint32_t v_off = (lane & 7) * PIT + ((lane >> 3) & 1) * 8 * PIT + (lane >> 4) * 16;

    #define AISSUE(st_, k0_)                                                   \
        {                                                                      \
            int r = tid >> 3, cc = tid & 7;                                    \
            uint32_t d = sb + (st_) * AST + r * PIT + cc * 16;                 \
            size_t g = ((size_t)(bT + (k0_) + r)) * DM_ + hcol + cc * 8;       \
            CP_ASYNC16(d,                  kq + g);                            \
            CP_ASYNC16(d + 32 * PIT,       kq + g + 32 * DM_);                 \
            CP_ASYNC16(d + V_O,            vq + g);                            \
            CP_ASYNC16(d + V_O + 32 * PIT, vq + g + 32 * DM_);                 \
            CP_COMMIT();                                                       \
        }

    #pragma unroll 1
    for (int ph = 0; ph < 2; ph++) {
        const int qi = ph ? bx : 15 - bx;     // heavy tile first
        const int q0 = qi * 128;
        const int nkt = 2 * qi + 2;
        const int qg_lo = q0 + wq * 16 + (lane >> 2);
        const int qg_hi = qg_lo + 8;

        __syncthreads();    // all warps done reading previous phase's smem

        // ---- stage Q through smem, extract A-fragments ----
        {
            int r = tid >> 3, c = tid & 7;
            #pragma unroll
            for (int i = 0; i < 4; i++) {
                int row = r + i * 32;
                size_t g = ((size_t)(bT + q0 + row)) * DM_ + hcol + c * 8;
                *(uint4*)(sm + row * PIT + c * 16) = *(const uint4*)(qq + g);
            }
        }
        __syncthreads();

        uint32_t qf[4][4];
        {
            const uint32_t a_off = (lane & 15) * PIT + (lane >> 4) * 16;
            #pragma unroll
            for (int ks = 0; ks < 4; ks++)
                ldsm4(qf[ks], sb + (wq * 16) * PIT + ks * 32 + a_off);
        }
        __syncthreads();   // Q reads done; smem reusable for K/V stages

        AISSUE(0, 0);
        if (nkt > 1) AISSUE(1, 64);

        float o[8][4];
        #pragma unroll
        for (int i = 0; i < 8; i++)
            #pragma unroll
            for (int j = 0; j < 4; j++) o[i][j] = 0.f;
        float l_lo = 0.f, l_hi = 0.f;

        for (int kt = 0; kt < nkt; kt++) {
            const int k0 = kt * 64;
            if (kt + 1 < nkt) { CP_WAIT1(); } else { CP_WAIT0(); }
            __syncthreads();
            if (kt + 2 < nkt) { AISSUE((kt + 2) % 3, (kt + 2) * 64); }

            const uint32_t stb = sb + (kt % 3) * AST;
            const bool diag = (kt >= nkt - 2);

            #pragma unroll
            for (int nt2 = 0; nt2 < 4; nt2++) {
                // ---- QK strip ----
                float s0[4] = {0.f, 0.f, 0.f, 0.f};
                float s1[4] = {0.f, 0.f, 0.f, 0.f};
                #pragma unroll
                for (int ks = 0; ks < 4; ks++) {
                    uint32_t th[4];
                    ldsm4(th, stb + (nt2 * 16) * PIT + ks * 32 + k_off);
                    mma16816h(s0, qf[ks], th);
                    mma16816h(s1, qf[ks], th + 2);
                }

                if (diag) {
                    int kg = k0 + nt2 * 16 + (lane & 3) * 2;
                    if (kg     > qg_lo) s0[0] = -1e30f;
                    if (kg + 1 > qg_lo) s0[1] = -1e30f;
                    if (kg     > qg_hi) s0[2] = -1e30f;
                    if (kg + 1 > qg_hi) s0[3] = -1e30f;
                    if (kg + 8 > qg_lo) s1[0] = -1e30f;
                    if (kg + 9 > qg_lo) s1[1] = -1e30f;
                    if (kg + 8 > qg_hi) s1[2] = -1e30f;
                    if (kg + 9 > qg_hi) s1[3] = -1e30f;
                }

                // ---- softmax strip ----
                s0[0] = ex2f(s0[0]); s0[1] = ex2f(s0[1]);
                s0[2] = ex2f(s0[2]); s0[3] = ex2f(s0[3]);
                s1[0] = ex2f(s1[0]); s1[1] = ex2f(s1[1]);
                s1[2] = ex2f(s1[2]); s1[3] = ex2f(s1[3]);
                l_lo += s0[0] + s0[1] + s1[0] + s1[1];
                l_hi += s0[2] + s0[3] + s1[2] + s1[3];

                uint32_t pf[4];
                pf[0] = pack_h2(s0[0], s0[1]);
                pf[1] = pack_h2(s0[2], s0[3]);
                pf[2] = pack_h2(s1[0], s1[1]);
                pf[3] = pack_h2(s1[2], s1[3]);

                // ---- PV strip ----
                #pragma unroll
                for (int d2 = 0; d2 < 4; d2++) {
                    uint32_t tv[4];
                    ldsm4t(tv, stb + V_O + (nt2 * 16) * PIT + d2 * 32 + v_off);
                    mma16816h(o[2*d2],   pf, tv);
                    mma16816h(o[2*d2+1], pf, tv + 2);
                }
            }
        }

        // ---- epilogue ----
        l_lo += __shfl_xor_sync(0xffffffffu, l_lo, 1);
        l_lo += __shfl_xor_sync(0xffffffffu, l_lo, 2);
        l_hi += __shfl_xor_sync(0xffffffffu, l_hi, 1);
        l_hi += __shfl_xor_sync(0xffffffffu, l_hi, 2);
        float il_lo = 1.f / l_lo, il_hi = 1.f / l_hi;
        size_t out_lo = ((size_t)(bT + qg_lo)) * DM_ + hcol + (lane & 3) * 2;
        #pragma unroll
        for (int nt = 0; nt < 8; nt++) {
            *(uint32_t*)(zq + out_lo + nt * 8) =
                pack_h2(o[nt][0] * il_lo, o[nt][1] * il_lo);
            *(uint32_t*)(zq + out_lo + 8 * DM_ + nt * 8) =
                pack_h2(o[nt][2] * il_hi, o[nt][3] * il_hi);
        }
    }
    #undef AISSUE
}

// ---------------------------------------------------------------------------
extern "C" void kernel_launch(void* const* d_in, const int* in_sizes, int n_in,
                              void* d_out, int out_size)
{
    const float* x  = (const float*)d_in[0];
    const float* cs = (const float*)d_in[1];
    const float* sn = (const float*)d_in[2];
    const float* Wq = (const float*)d_in[3];
    const float* Wk = (const float*)d_in[4];
    const float* Wv = (const float*)d_in[5];
    const float* Wo = (const float*)d_in[6];
    float* out = (float*)d_out;

    __half *xp, *wp, *qp, *kp, *vp, *zp;
    cudaGetSymbolAddress((void**)&xp, g_x);
    cudaGetSymbolAddress((void**)&wp, g_w);
    cudaGetSymbolAddress((void**)&qp, g_q);
    cudaGetSymbolAddress((void**)&kp, g_k);
    cudaGetSymbolAddress((void**)&vp, g_v);
    cudaGetSymbolAddress((void**)&zp, g_z);

    cudaFuncSetAttribute(gemm128<0>, cudaFuncAttributeMaxDynamicSharedMemorySize, G_SMEM);
    cudaFuncSetAttribute(gemm128<1>, cudaFuncAttributeMaxDynamicSharedMemorySize, G_SMEM);
    cudaFuncSetAttribute(attn_mma, cudaFuncAttributeMaxDynamicSharedMemorySize, ATT_SMEM);

    // fp32 -> fp16 conversions (one launch)
    conv_all<<<dim3(1024, 8), 256>>>(x, Wq, Wk, Wv, Wo, xp, wp);

    // fused QKV GEMM + RoPE epilogue (768 CTAs — R12 launch shape)
    gemm128<0><<<dim3(24, BT_ / 128), 256, G_SMEM>>>(
        xp, wp, cs, sn, nullptr, qp, kp, vp);

    attn_mma<<<dim3(8, B_ * H_), 256, ATT_SMEM>>>(qp, kp, vp, zp);

    // out = z Wo
    gemm128<1><<<dim3(8, BT_ / 128), 256, G_SMEM>>>(
        zp, wp, cs, sn, out, nullptr, nullptr, nullptr);
}

// round 16
// speedup vs baseline: 1.2477x; 1.2477x over previous
#include <cuda_runtime.h>
#include <cuda_fp16.h>
#include <cstdint>

#define B_   2
#define T_   2048
#define DM_  1024
#define H_   16
#define DH_  64
#define BT_  (B_ * T_)   // 4096

// Scratch (allocation-free rule: device globals) — all single fp16
__device__ __half g_x[BT_ * DM_];
__device__ __half g_w[4 * DM_ * DM_];                 // W fp16, [K,N], 4 slabs
__device__ __half g_q[BT_ * DM_];
__device__ __half g_k[BT_ * DM_];
__device__ __half g_v[BT_ * DM_];
__device__ __half g_z[BT_ * DM_];

// ===========================================================================
// Warp-MMA + cp.async helpers
// ===========================================================================
__device__ __forceinline__ uint32_t smem_u32(const void* p) {
    uint32_t a;
    asm("{ .reg .u64 t; cvta.to.shared.u64 t, %1; cvt.u32.u64 %0, t; }"
        : "=r"(a) : "l"(p));
    return a;
}

__device__ __forceinline__ void ldsm4(uint32_t* r, uint32_t addr) {
    asm volatile("ldmatrix.sync.aligned.m8n8.x4.shared.b16 {%0,%1,%2,%3}, [%4];"
                 : "=r"(r[0]), "=r"(r[1]), "=r"(r[2]), "=r"(r[3]) : "r"(addr));
}
__device__ __forceinline__ void ldsm4t(uint32_t* r, uint32_t addr) {
    asm volatile("ldmatrix.sync.aligned.m8n8.x4.trans.shared.b16 {%0,%1,%2,%3}, [%4];"
                 : "=r"(r[0]), "=r"(r[1]), "=r"(r[2]), "=r"(r[3]) : "r"(addr));
}

__device__ __forceinline__ void mma16816h(float* c, const uint32_t* a,
                                          const uint32_t* b) {
    asm volatile(
        "mma.sync.aligned.m16n8k16.row.col.f32.f16.f16.f32 "
        "{%0,%1,%2,%3}, {%4,%5,%6,%7}, {%8,%9}, {%0,%1,%2,%3};"
        : "+f"(c[0]), "+f"(c[1]), "+f"(c[2]), "+f"(c[3])
        : "r"(a[0]), "r"(a[1]), "r"(a[2]), "r"(a[3]), "r"(b[0]), "r"(b[1]));
}

#define CP_ASYNC16(dst, src) \
    asm volatile("cp.async.cg.shared.global [%0], [%1], 16;" :: "r"(dst), "l"(src))
#define CP_COMMIT() asm volatile("cp.async.commit_group;")
#define CP_WAIT1()  asm volatile("cp.async.wait_group 1;")
#define CP_WAIT0()  asm volatile("cp.async.wait_group 0;")

__device__ __forceinline__ float ex2f(float x) {
    float y;
    asm("ex2.approx.f32 %0, %1;" : "=f"(y) : "f"(x));
    return y;
}

__device__ __forceinline__ uint32_t pack_h2(float x, float y) {
    __half2 h = __floats2half2_rn(x, y);
    return *(uint32_t*)&h;
}

// ===========================================================================
// Fused conversion kernel (x + 4 weight slabs), fp32 -> fp16
// ===========================================================================
__global__ void conv_all(const float* __restrict__ x,
                         const float* __restrict__ W0, const float* __restrict__ W1,
                         const float* __restrict__ W2, const float* __restrict__ W3,
                         __half* __restrict__ xo, __half* __restrict__ wo)
{
    int y = blockIdx.y;
    if (y < 4) {
        const float* src = (y == 0) ? W0 : (y == 1) ? W1 : (y == 2) ? W2 : W3;
        size_t i = (size_t)(blockIdx.x * 256 + threadIdx.x) * 4;
        float4 v = *(const float4*)(src + i);
        *(uint2*)(wo + (size_t)y * DM_ * DM_ + i) =
            make_uint2(pack_h2(v.x, v.y), pack_h2(v.z, v.w));
    } else {
        size_t i = ((size_t)(y - 4) * 1024 + blockIdx.x) * 1024 +
                   (size_t)threadIdx.x * 4;
        float4 v = *(const float4*)(x + i);
        *(uint2*)(xo + i) = make_uint2(pack_h2(v.x, v.y), pack_h2(v.z, v.w));
    }
}

// ===========================================================================
// fp16 single-pass GEMM: 128x128 tile, BK=32, cp.async 3-stage ring,
// one __syncthreads per k-iteration. 2 CTA/SM.  (R12 configuration)
// MODE 0: QKV (widx = blockIdx.x>>3) — RoPE epilogue. MODE 1: out-proj.
// ===========================================================================
#define GP      80
#define TSZA    (128 * GP)            // 10240
#define PITB    272
#define TSZB    (32 * PITB)           // 8704
#define STG     (TSZA + TSZB)         // 18944 per stage
#define G_SMEM  (3 * STG)             // 56832

#define QSCALE  0.1803368801111204f   // 0.125 * log2(e)

template<int MODE>
__global__ __launch_bounds__(256, 2) void gemm128(
    const __half* __restrict__ Ap, const __half* __restrict__ Wp,
    const float* __restrict__ cs, const float* __restrict__ sn,
    float* __restrict__ Cf,
    __half* __restrict__ qq, __half* __restrict__ kq, __half* __restrict__ vq)
{
    extern __shared__ __align__(16) char sm[];
    const int tid  = threadIdx.x;
    const int wid  = tid >> 5;
    const int lane = tid & 31;
    const int wm   = wid & 3;
    const int wn   = wid >> 2;
    const int widx = (MODE == 0) ? (blockIdx.x >> 3) : 3;
    const int n0   = (blockIdx.x & 7) * 128;
    const int m0   = blockIdx.y * 128;
    const uint32_t sb = smem_u32(sm);

    const __half* gA = Ap + (size_t)m0 * DM_;
    const __half* gW = Wp + (size_t)widx * DM_ * DM_ + n0;

    const int arow = tid >> 2;
    const int acg  = tid & 3;
    const int brow = tid >> 4;
    const int bcg  = tid & 15;

    #define ISSUE(st_, k0_)                                                    \
        {                                                                      \
            uint32_t dA = sb + (st_) * STG + arow * GP + acg * 16;             \
            const __half* ga = gA + (size_t)arow * DM_ + (k0_) + acg * 8;      \
            CP_ASYNC16(dA,           ga);                                      \
            CP_ASYNC16(dA + 64 * GP, ga + (size_t)64 * DM_);                   \
            uint32_t dB = sb + (st_) * STG + TSZA + brow * PITB + bcg * 16;    \
            const __half* gb = gW + (size_t)((k0_) + brow) * DM_ + bcg * 8;    \
            CP_ASYNC16(dB,             gb);                                    \
            CP_ASYNC16(dB + 16 * PITB, gb + (size_t)16 * DM_);                 \
            CP_COMMIT();                                                       \
        }

    const uint32_t a_off = (uint32_t)((lane & 15) * GP + (lane >> 4) * 16);
    const uint32_t b_off = (uint32_t)((lane & 7) * PITB +
                                      ((lane >> 3) & 1) * 8 * PITB + (lane >> 4) * 16);

    float acc[2][8][4];
    #pragma unroll
    for (int i = 0; i < 2; i++)
        #pragma unroll
        for (int j = 0; j < 8; j++)
            #pragma unroll
            for (int l = 0; l < 4; l++) acc[i][j][l] = 0.f;

    ISSUE(0, 0);
    ISSUE(1, 32);

    const int NIT = DM_ / 32;   // 32
    for (int c = 0; c < NIT; c++) {
        if (c + 1 < NIT) { CP_WAIT1(); } else { CP_WAIT0(); }
        __syncthreads();
        if (c + 2 < NIT) { ISSUE((c + 2) % 3, (c + 2) * 32); }

        const uint32_t stb = sb + (c % 3) * STG;
        #pragma unroll
        for (int ks = 0; ks < 2; ks++) {
            uint32_t af[2][4];
            #pragma unroll
            for (int mt = 0; mt < 2; mt++)
                ldsm4(af[mt], stb + (uint32_t)((wm * 32 + mt * 16) * GP + ks * 32) + a_off);
            #pragma unroll
            for (int nt = 0; nt < 4; nt++) {
                uint32_t bb = stb + TSZA + (uint32_t)(ks * 16 * PITB +
                              wn * 128 + nt * 32) + b_off;
                uint32_t th[4];
                ldsm4t(th, bb);
                #pragma unroll
                for (int mt = 0; mt < 2; mt++) {
                    mma16816h(acc[mt][2*nt],   af[mt], th);
                    mma16816h(acc[mt][2*nt+1], af[mt], th + 2);
                }
            }
        }
    }

    // ---- epilogue ----
    if (MODE == 1) {
        #pragma unroll
        for (int mt = 0; mt < 2; mt++) {
            int m = m0 + wm * 32 + mt * 16 + (lane >> 2);
            #pragma unroll
            for (int nt = 0; nt < 8; nt++) {
                int n = n0 + wn * 64 + nt * 8 + (lane & 3) * 2;
                *(float2*)(Cf + (size_t)m * DM_ + n) =
                    make_float2(acc[mt][nt][0], acc[mt][nt][1]);
                *(float2*)(Cf + (size_t)(m + 8) * DM_ + n) =
                    make_float2(acc[mt][nt][2], acc[mt][nt][3]);
            }
        }
    } else {
        __half* d = (widx == 0) ? qq : (widx == 1) ? kq : vq;
        #pragma unroll
        for (int mt = 0; mt < 2; mt++) {
            int m  = m0 + wm * 32 + mt * 16 + (lane >> 2);
            int t0 = m & (T_ - 1);
            int t1 = (m + 8) & (T_ - 1);
            #pragma unroll
            for (int nt = 0; nt < 8; nt++) {
                int n = n0 + wn * 64 + nt * 8 + (lane & 3) * 2;
                float e0 = acc[mt][nt][0], o0 = acc[mt][nt][1];
                float e1 = acc[mt][nt][2], o1 = acc[mt][nt][3];
                if (widx <= 1) {
                    int i = (n & 63) >> 1;
                    float c0 = __ldg(cs + t0 * 32 + i), s0 = __ldg(sn + t0 * 32 + i);
                    float c1 = __ldg(cs + t1 * 32 + i), s1 = __ldg(sn + t1 * 32 + i);
                    float sc = (widx == 0) ? QSCALE : 1.f;
                    float a0 = (e0 * c0 - o0 * s0) * sc, b0 = (e0 * s0 + o0 * c0) * sc;
                    float a1 = (e1 * c1 - o1 * s1) * sc, b1 = (e1 * s1 + o1 * c1) * sc;
                    e0 = a0; o0 = b0; e1 = a1; o1 = b1;
                }
                *(uint32_t*)(d + (size_t)m * DM_ + n)       = pack_h2(e0, o0);
                *(uint32_t*)(d + (size_t)(m + 8) * DM_ + n) = pack_h2(e1, o1);
            }
        }
    }
    #undef ISSUE
}

// ===========================================================================
// Tensor-core flash attention (fp16 single-pass, causal, exp2 SOFF=0).
// R12 core + dedicated Q smem region: per phase, K/V stage-0/1 cp.async are
// issued BEFORE Q staging, overlapping their global latency with the Q
// stage + fragment extraction. One fewer __syncthreads per phase.
// Balanced CTA pairs (15-bx, bx): 34 k-tiles each; 2 CTA/SM.
// ===========================================================================
#define PIT    144
#define V_O    9216
#define AST    18432                // ring stage size (K + V tiles)
#define Q_SZ   18432                // dedicated Q region (128 rows x PIT)
#define RING_O Q_SZ                 // ring starts after Q region
#define ATT_SMEM (Q_SZ + 3 * AST)   // 73728

__global__ __launch_bounds__(256, 2) void attn_mma(
    const __half* __restrict__ qq, const __half* __restrict__ kq,
    const __half* __restrict__ vq, __half* __restrict__ zq)
{
    extern __shared__ __align__(16) char sm[];
    const int tid  = threadIdx.x;
    const int lane = tid & 31;
    const int wq   = tid >> 5;
    const int bx   = blockIdx.x;          // 0..7
    const int bh_  = blockIdx.y;
    const int b    = bh_ >> 4;
    const int h    = bh_ & 15;
    const int bT   = b * T_;
    const uint32_t sb = smem_u32(sm);
    const size_t hcol = (size_t)h * DH_;

    const uint32_t k_off = ((lane >> 4) * 8 + (lane & 7)) * PIT + ((lane >> 3) & 1) * 16;
    const uint32_t v_off = (lane & 7) * PIT + ((lane >> 3) & 1) * 8 * PIT + (lane >> 4) * 16;

    #define AISSUE(st_, k0_)                                                   \
        {                                                                      \
            int r = tid >> 3, cc = tid & 7;                                    \
            uint32_t d = sb + RING_O + (st_) * AST + r * PIT + cc * 16;        \
            size_t g = ((size_t)(bT + (k0_) + r)) * DM_ + hcol + cc * 8;       \
            CP_ASYNC16(d,                  kq + g);                            \
            CP_ASYNC16(d + 32 * PIT,       kq + g + 32 * DM_);                 \
            CP_ASYNC16(d + V_O,            vq + g);                            \
            CP_ASYNC16(d + V_O + 32 * PIT, vq + g + 32 * DM_);                 \
            CP_COMMIT();                                                       \
        }

    #pragma unroll 1
    for (int ph = 0; ph < 2; ph++) {
        const int qi = ph ? bx : 15 - bx;     // heavy tile first
        const int q0 = qi * 128;
        const int nkt = 2 * qi + 2;
        const int qg_lo = q0 + wq * 16 + (lane >> 2);
        const int qg_hi = qg_lo + 8;

        // Phase boundary: previous phase's ring reads + Q-region reads done.
        __syncthreads();

        // Kick off K/V stages 0,1 first — their latency overlaps Q staging.
        AISSUE(0, 0);
        if (nkt > 1) AISSUE(1, 64);

        // ---- stage Q into dedicated region ----
        {
            int r = tid >> 3, c = tid & 7;
            #pragma unroll
            for (int i = 0; i < 4; i++) {
                int row = r + i * 32;
                size_t g = ((size_t)(bT + q0 + row)) * DM_ + hcol + c * 8;
                *(uint4*)(sm + row * PIT + c * 16) = *(const uint4*)(qq + g);
            }
        }
        __syncthreads();

        uint32_t qf[4][4];
        {
            const uint32_t a_off = (lane & 15) * PIT + (lane >> 4) * 16;
            #pragma unroll
            for (int ks = 0; ks < 4; ks++)
                ldsm4(qf[ks], sb + (wq * 16) * PIT + ks * 32 + a_off);
        }
        // (no sync needed: Q region is dedicated; next overwrite is after
        //  the phase-boundary sync above)

        float o[8][4];
        #pragma unroll
        for (int i = 0; i < 8; i++)
            #pragma unroll
            for (int j = 0; j < 4; j++) o[i][j] = 0.f;
        float l_lo = 0.f, l_hi = 0.f;

        for (int kt = 0; kt < nkt; kt++) {
            const int k0 = kt * 64;
            if (kt + 1 < nkt) { CP_WAIT1(); } else { CP_WAIT0(); }
            __syncthreads();
            if (kt + 2 < nkt) { AISSUE((kt + 2) % 3, (kt + 2) * 64); }

            const uint32_t stb = sb + RING_O + (kt % 3) * AST;
            const bool diag = (kt >= nkt - 2);

            #pragma unroll
            for (int nt2 = 0; nt2 < 4; nt2++) {
                // ---- QK strip ----
                float s0[4] = {0.f, 0.f, 0.f, 0.f};
                float s1[4] = {0.f, 0.f, 0.f, 0.f};
                #pragma unroll
                for (int ks = 0; ks < 4; ks++) {
                    uint32_t th[4];
                    ldsm4(th, stb + (nt2 * 16) * PIT + ks * 32 + k_off);
                    mma16816h(s0, qf[ks], th);
                    mma16816h(s1, qf[ks], th + 2);
                }

                if (diag) {
                    int kg = k0 + nt2 * 16 + (lane & 3) * 2;
                    if (kg     > qg_lo) s0[0] = -1e30f;
                    if (kg + 1 > qg_lo) s0[1] = -1e30f;
                    if (kg     > qg_hi) s0[2] = -1e30f;
                    if (kg + 1 > qg_hi) s0[3] = -1e30f;
                    if (kg + 8 > qg_lo) s1[0] = -1e30f;
                    if (kg + 9 > qg_lo) s1[1] = -1e30f;
                    if (kg + 8 > qg_hi) s1[2] = -1e30f;
                    if (kg + 9 > qg_hi) s1[3] = -1e30f;
                }

                // ---- softmax strip ----
                s0[0] = ex2f(s0[0]); s0[1] = ex2f(s0[1]);
                s0[2] = ex2f(s0[2]); s0[3] = ex2f(s0[3]);
                s1[0] = ex2f(s1[0]); s1[1] = ex2f(s1[1]);
                s1[2] = ex2f(s1[2]); s1[3] = ex2f(s1[3]);
                l_lo += s0[0] + s0[1] + s1[0] + s1[1];
                l_hi += s0[2] + s0[3] + s1[2] + s1[3];

                uint32_t pf[4];
                pf[0] = pack_h2(s0[0], s0[1]);
                pf[1] = pack_h2(s0[2], s0[3]);
                pf[2] = pack_h2(s1[0], s1[1]);
                pf[3] = pack_h2(s1[2], s1[3]);

                // ---- PV strip ----
                #pragma unroll
                for (int d2 = 0; d2 < 4; d2++) {
                    uint32_t tv[4];
                    ldsm4t(tv, stb + V_O + (nt2 * 16) * PIT + d2 * 32 + v_off);
                    mma16816h(o[2*d2],   pf, tv);
                    mma16816h(o[2*d2+1], pf, tv + 2);
                }
            }
        }

        // ---- epilogue ----
        l_lo += __shfl_xor_sync(0xffffffffu, l_lo, 1);
        l_lo += __shfl_xor_sync(0xffffffffu, l_lo, 2);
        l_hi += __shfl_xor_sync(0xffffffffu, l_hi, 1);
        l_hi += __shfl_xor_sync(0xffffffffu, l_hi, 2);
        float il_lo = 1.f / l_lo, il_hi = 1.f / l_hi;
        size_t out_lo = ((size_t)(bT + qg_lo)) * DM_ + hcol + (lane & 3) * 2;
        #pragma unroll
        for (int nt = 0; nt < 8; nt++) {
            *(uint32_t*)(zq + out_lo + nt * 8) =
                pack_h2(o[nt][0] * il_lo, o[nt][1] * il_lo);
            *(uint32_t*)(zq + out_lo + 8 * DM_ + nt * 8) =
                pack_h2(o[nt][2] * il_hi, o[nt][3] * il_hi);
        }
    }
    #undef AISSUE
}

// ---------------------------------------------------------------------------
extern "C" void kernel_launch(void* const* d_in, const int* in_sizes, int n_in,
                              void* d_out, int out_size)
{
    const float* x  = (const float*)d_in[0];
    const float* cs = (const float*)d_in[1];
    const float* sn = (const float*)d_in[2];
    const float* Wq = (const float*)d_in[3];
    const float* Wk = (const float*)d_in[4];
    const float* Wv = (const float*)d_in[5];
    const float* Wo = (const float*)d_in[6];
    float* out = (float*)d_out;

    __half *xp, *wp, *qp, *kp, *vp, *zp;
    cudaGetSymbolAddress((void**)&xp, g_x);
    cudaGetSymbolAddress((void**)&wp, g_w);
    cudaGetSymbolAddress((void**)&qp, g_q);
    cudaGetSymbolAddress((void**)&kp, g_k);
    cudaGetSymbolAddress((void**)&vp, g_v);
    cudaGetSymbolAddress((void**)&zp, g_z);

    cudaFuncSetAttribute(gemm128<0>, cudaFuncAttributeMaxDynamicSharedMemorySize, G_SMEM);
    cudaFuncSetAttribute(gemm128<1>, cudaFuncAttributeMaxDynamicSharedMemorySize, G_SMEM);
    cudaFuncSetAttribute(attn_mma, cudaFuncAttributeMaxDynamicSharedMemorySize, ATT_SMEM);

    // fp32 -> fp16 conversions (one launch)
    conv_all<<<dim3(1024, 8), 256>>>(x, Wq, Wk, Wv, Wo, xp, wp);

    // fused QKV GEMM + RoPE epilogue (R12 launch shape)
    gemm128<0><<<dim3(24, BT_ / 128), 256, G_SMEM>>>(
        xp, wp, cs, sn, nullptr, qp, kp, vp);

    attn_mma<<<dim3(8, B_ * H_), 256, ATT_SMEM>>>(qp, kp, vp, zp);

    // out = z Wo
    gemm128<1><<<dim3(8, BT_ / 128), 256, G_SMEM>>>(
        zp, wp, cs, sn, out, nullptr, nullptr, nullptr);
}